// round 11
// baseline (speedup 1.0000x reference)
#include <cuda_runtime.h>
#include <cuda_fp16.h>
#include <math.h>
#include <stdint.h>

#define TOKENS 4096
#define DMODEL 1024
#define DINNER 2048
#define DSTATE 16
#define SEQL   2048

// Scratch (static device globals — no runtime allocation allowed)
__device__ __align__(256) float  g_xz [TOKENS * 2 * DINNER];  // GEMM1 out: xi-preconv | z
__device__ __align__(256) float  g_xi [TOKENS * DINNER];      // conv+silu output (fp32)
__device__ __align__(256) float  g_dbc[TOKENS * 33];
__device__ __align__(256) float  g_dbcp[8][TOKENS * 33];
__device__ __align__(256) __half g_xh [TOKENS * DMODEL];      // half x
__device__ __align__(256) __half g_wh [2 * DINNER * DMODEL];  // half W_in
__device__ __align__(256) __half g_woh[DMODEL * DINNER];      // half W_out
__device__ __align__(256) __half g_yh [TOKENS * DINNER];      // half scan output

// Segmented-scan state: [b][seg][d][n]
#define SEGTOK 128
#define NSEG (SEQL / SEGTOK)               // 16
__device__ __align__(256) float g_P    [2 * NSEG * DINNER * DSTATE];
__device__ __align__(256) float g_hend [2 * NSEG * DINNER * DSTATE];
__device__ __align__(256) float g_hst  [2 * NSEG * DINNER * DSTATE];

// ---------------------------------------------------------------------------
__device__ __forceinline__ void cp_async16(void* smem_dst, const void* gmem_src) {
    uint32_t s = (uint32_t)__cvta_generic_to_shared(smem_dst);
    asm volatile("cp.async.cg.shared.global [%0], [%1], 16;" :: "r"(s), "l"(gmem_src));
}

__device__ __forceinline__ void mma_f16(float* c, const uint32_t* a, const uint32_t* b) {
    asm volatile(
        "mma.sync.aligned.m16n8k16.row.col.f32.f16.f16.f32 "
        "{%0,%1,%2,%3}, {%4,%5,%6,%7}, {%8,%9}, {%0,%1,%2,%3};"
        : "+f"(c[0]), "+f"(c[1]), "+f"(c[2]), "+f"(c[3])
        : "r"(a[0]), "r"(a[1]), "r"(a[2]), "r"(a[3]), "r"(b[0]), "r"(b[1]));
}

__device__ __forceinline__ void ldsm_x4(uint32_t& r0, uint32_t& r1, uint32_t& r2,
                                        uint32_t& r3, uint32_t saddr) {
    asm volatile("ldmatrix.sync.aligned.m8n8.x4.shared.b16 {%0,%1,%2,%3}, [%4];"
        : "=r"(r0), "=r"(r1), "=r"(r2), "=r"(r3) : "r"(saddr));
}

// ---------------------------------------------------------------------------
// FP16 mma.sync GEMM with ldmatrix (unchanged): BM=BN=128, BK=64, 2 CTAs/SM.
// ---------------------------------------------------------------------------
#define BM 128
#define BN 128
#define BK 64
#define STRH 72
#define A_HALFS (BM * STRH)
#define B_HALFS (BN * STRH)
#define STG_HALFS (A_HALFS + B_HALFS)
#define GEMM_SMEM (3 * STG_HALFS * 2)        // 110592 B

__global__ void __launch_bounds__(256, 2)
h_gemm_nt(const __half* __restrict__ A, const __half* __restrict__ B,
          float* __restrict__ C, int M, int N, int K) {
    extern __shared__ __half sh[];
    constexpr int WN = 32;
    constexpr int NFN = 4;
    constexpr int NPAIR = 2;

    const int tid  = threadIdx.x;
    const int wid  = tid >> 5;
    const int lane = tid & 31;
    const int gid  = lane >> 2;
    const int t4   = lane & 3;
    const int wm   = wid & 1;
    const int wn   = wid >> 1;
    const int row0 = blockIdx.y * BM;
    const int col0 = blockIdx.x * BN;

    const uint32_t sbase = (uint32_t)__cvta_generic_to_shared(sh);

    const int a_row  = wm * 64 + (lane & 15);
    const int a_colh = (lane >> 4) * 8;
    const int b_row  = (lane & 7) + ((lane >> 4) * 8);
    const int b_colh = ((lane >> 3) & 1) * 8;

    const int lrow = tid >> 3;
    const int lchk = (tid & 7) * 8;

    float acc[4][NFN][4] = {};
    const int niter = K / BK;

    auto load_stage = [&](int stage, int k0) {
        __half* Sa = sh + stage * STG_HALFS;
        __half* Sb = Sa + A_HALFS;
#pragma unroll
        for (int i = 0; i < BM / 32; i++) {
            int r = lrow + i * 32;
            cp_async16(&Sa[r * STRH + lchk], A + (size_t)(row0 + r) * K + k0 + lchk);
        }
#pragma unroll
        for (int i = 0; i < BN / 32; i++) {
            int r = lrow + i * 32;
            cp_async16(&Sb[r * STRH + lchk], B + (size_t)(col0 + r) * K + k0 + lchk);
        }
    };

    load_stage(0, 0);
    asm volatile("cp.async.commit_group;");
    if (niter > 1) load_stage(1, BK);
    asm volatile("cp.async.commit_group;");

    int s = 0;
    for (int it = 0; it < niter; it++) {
        asm volatile("cp.async.wait_group 1;");
        __syncthreads();

        if (it + 2 < niter) load_stage((it + 2) % 3, (it + 2) * BK);
        asm volatile("cp.async.commit_group;");

        const uint32_t sA = sbase + (uint32_t)(s * STG_HALFS) * 2;
        const uint32_t sB = sA + A_HALFS * 2;
#pragma unroll
        for (int kk = 0; kk < BK / 16; kk++) {
            const int kb = kk * 16;
            uint32_t af[4][4], bf[NFN][2];
#pragma unroll
            for (int fm = 0; fm < 4; fm++)
                ldsm_x4(af[fm][0], af[fm][1], af[fm][2], af[fm][3],
                        sA + (uint32_t)((a_row + fm * 16) * STRH + kb + a_colh) * 2);
#pragma unroll
            for (int p = 0; p < NPAIR; p++)
                ldsm_x4(bf[2 * p][0], bf[2 * p][1], bf[2 * p + 1][0], bf[2 * p + 1][1],
                        sB + (uint32_t)((wn * WN + p * 16 + b_row) * STRH + kb + b_colh) * 2);
#pragma unroll
            for (int fm = 0; fm < 4; fm++)
#pragma unroll
                for (int fn = 0; fn < NFN; fn++)
                    mma_f16(acc[fm][fn], af[fm], bf[fn]);
        }
        __syncthreads();
        s = (s + 1) % 3;
    }

#pragma unroll
    for (int fm = 0; fm < 4; fm++) {
        int r = row0 + wm * 64 + fm * 16 + gid;
#pragma unroll
        for (int fn = 0; fn < NFN; fn++) {
            int cbase = col0 + wn * WN + fn * 8 + t4 * 2;
            float2* p0 = (float2*)&C[(size_t)r * N + cbase];
            float2* p1 = (float2*)&C[(size_t)(r + 8) * N + cbase];
            *p0 = make_float2(acc[fm][fn][0], acc[fm][fn][1]);
            *p1 = make_float2(acc[fm][fn][2], acc[fm][fn][3]);
        }
    }
}

// ---------------------------------------------------------------------------
// Fused fp32->fp16 conversion of x, W_in, W_out (one launch)
// ---------------------------------------------------------------------------
#define N4_X  (TOKENS * DMODEL / 4)
#define N4_WI (2 * DINNER * DMODEL / 4)
#define N4_WO (DMODEL * DINNER / 4)

__global__ void cvt_all_k(const float* __restrict__ x, const float* __restrict__ Wi,
                          const float* __restrict__ Wo) {
    int i = blockIdx.x * blockDim.x + threadIdx.x;
    const float* src; __half* dst; int off;
    if (i < N4_X)                  { src = x;  dst = g_xh;  off = i; }
    else if (i < N4_X + N4_WI)     { src = Wi; dst = g_wh;  off = i - N4_X; }
    else if (i < N4_X + N4_WI + N4_WO) { src = Wo; dst = g_woh; off = i - N4_X - N4_WI; }
    else return;
    float4 v = ((const float4*)src)[off];
    __half2 h0 = __float22half2_rn(make_float2(v.x, v.y));
    __half2 h1 = __float22half2_rn(make_float2(v.z, v.w));
    ((uint2*)dst)[off] = make_uint2(*(uint32_t*)&h0, *(uint32_t*)&h1);
}

// ---------------------------------------------------------------------------
// Causal depthwise conv (width 4) + bias + SiLU on first half of xz -> g_xi
// ---------------------------------------------------------------------------
__global__ void conv_silu_k(const float* __restrict__ cw, const float* __restrict__ cb) {
    int idx = blockIdx.x * blockDim.x + threadIdx.x;
    int d = idx & (DINNER - 1);
    int t = idx >> 11;
    int l = t & (SEQL - 1);
    float w0 = cw[d * 4 + 0], w1 = cw[d * 4 + 1], w2 = cw[d * 4 + 2], w3 = cw[d * 4 + 3];
    float acc = cb[d];
    size_t base = (size_t)t * (2 * DINNER) + d;
    if (l >= 3) acc += g_xz[base - 3 * (size_t)(2 * DINNER)] * w0;
    if (l >= 2) acc += g_xz[base - 2 * (size_t)(2 * DINNER)] * w1;
    if (l >= 1) acc += g_xz[base - 1 * (size_t)(2 * DINNER)] * w2;
    acc += g_xz[base] * w3;
    g_xi[idx] = acc / (1.f + __expf(-acc));
}

// ---------------------------------------------------------------------------
// x_dbl split-K partials + deterministic reduce (unchanged from R10)
// ---------------------------------------------------------------------------
__global__ void xdbl_part_k(const float* __restrict__ Wx) {
    __shared__ float Xs[32][72];
    __shared__ float Ws[33][33];
    const int tx = threadIdx.x, ty = threadIdx.y;   // (33,8)
    const int tid = ty * 33 + tx;
    const int tok0 = blockIdx.x * 64;
    const int kbase = blockIdx.y * 256;
    float acc[8] = {};
    for (int k0 = kbase; k0 < kbase + 256; k0 += 32) {
        for (int i = tid; i < 64 * 32; i += 264) {
            int tt = i >> 5, kk = i & 31;
            Xs[kk][tt] = g_xi[(size_t)(tok0 + tt) * DINNER + k0 + kk];
        }
        for (int i = tid; i < 33 * 32; i += 264) {
            int e = i >> 5, kk = i & 31;
            Ws[e][kk] = Wx[(size_t)e * DINNER + k0 + kk];
        }
        __syncthreads();
#pragma unroll
        for (int kk = 0; kk < 32; kk++) {
            float w = Ws[tx][kk];
            const float4* xr = (const float4*)&Xs[kk][ty * 8];
            float4 x0 = xr[0], x1 = xr[1];
            acc[0] += x0.x * w; acc[1] += x0.y * w;
            acc[2] += x0.z * w; acc[3] += x0.w * w;
            acc[4] += x1.x * w; acc[5] += x1.y * w;
            acc[6] += x1.z * w; acc[7] += x1.w * w;
        }
        __syncthreads();
    }
#pragma unroll
    for (int i = 0; i < 8; i++)
        g_dbcp[blockIdx.y][(size_t)(tok0 + ty * 8 + i) * 33 + tx] = acc[i];
}

__global__ void xdbl_reduce_k() {
    int i = blockIdx.x * blockDim.x + threadIdx.x;
    if (i >= TOKENS * 33) return;
    float s = 0.f;
#pragma unroll
    for (int p = 0; p < 8; p++) s += g_dbcp[p][i];
    g_dbc[i] = s;
}

// ---------------------------------------------------------------------------
// Segmented selective scan.
// Pass 1: per segment, local h-recurrence from 0; stores decay product P and
//         local h_end per (b,seg,d,n). No C/z/output work.
// Fix:    tiny sequential pass over segments -> h_start per segment.
// Pass 2: full scan per segment starting from h_start (y, gating, output).
// ---------------------------------------------------------------------------
#define CH 32
#define CPB 8
#define PSTRIDE 17
#define CH_SEG (SEGTOK / CH)               // 4 chunks per segment

__global__ void __launch_bounds__(128)
scan_pass1(const float* __restrict__ A_log,
           const float* __restrict__ Wdt, const float* __restrict__ bdt) {
    __shared__ float sB[CH][16];
    __shared__ float sX[CH][CPB], sDT[CH][CPB];
    const int tid = threadIdx.x;              // 128
    const int dd = tid >> 4, n = tid & 15;
    const int q8 = tid & 7;
    const int b = blockIdx.z, seg = blockIdx.y;
    const int d0 = blockIdx.x * CPB;

    const float a  = -__expf(A_log[(d0 + dd) * DSTATE + n]);
    const float wq = Wdt[d0 + q8];
    const float bq = bdt[d0 + q8];
    float h = 0.f, P = 1.f;

    float rdbc[5], rx[2], rdt[2];
    auto prefetch = [&](int c) {
        const int tok0 = b * SEQL + seg * SEGTOK + c * CH;
#pragma unroll
        for (int j = 0; j < 5; j++) {
            int i = tid + j * 128;
            if (i < CH * 17) {
                int tt = i / 17, e = i - tt * 17;
                rdbc[j] = g_dbc[(size_t)(tok0 + tt) * 33 + e];
            }
        }
#pragma unroll
        for (int j = 0; j < 2; j++) {
            int tt = (tid + j * 128) >> 3;
            rx[j]  = g_xi[(size_t)(tok0 + tt) * DINNER + d0 + q8];
            rdt[j] = g_dbc[(size_t)(tok0 + tt) * 33];
        }
    };
    auto commit = [&]() {
#pragma unroll
        for (int j = 0; j < 5; j++) {
            int i = tid + j * 128;
            if (i < CH * 17) {
                int tt = i / 17, e = i - tt * 17;
                if (e >= 1) sB[tt][e - 1] = rdbc[j];
            }
        }
#pragma unroll
        for (int j = 0; j < 2; j++) {
            int tt = (tid + j * 128) >> 3;
            sX[tt][q8] = rx[j];
            float u = rdt[j] * wq + bq;
            sDT[tt][q8] = (u > 20.f) ? u : log1pf(__expf(u));
        }
    };

    prefetch(0);
    for (int c = 0; c < CH_SEG; c++) {
        commit();
        __syncthreads();
        if (c + 1 < CH_SEG) prefetch(c + 1);
        float dA[CH], bx[CH];
#pragma unroll
        for (int t = 0; t < CH; t++) {
            float dtv = sDT[t][dd];
            dA[t] = __expf(dtv * a);
            bx[t] = (dtv * sB[t][n]) * sX[t][dd];
        }
#pragma unroll
        for (int t = 0; t < CH; t++) {
            h = fmaf(dA[t], h, bx[t]);
            P *= dA[t];
        }
        __syncthreads();
    }
    size_t idx = ((size_t)(b * NSEG + seg) * DINNER + d0 + dd) * DSTATE + n;
    g_P[idx] = P;
    g_hend[idx] = h;
}

__global__ void scan_fix_k() {
    int i = blockIdx.x * blockDim.x + threadIdx.x;   // (b*DINNER + d)*16 + n
    if (i >= 2 * DINNER * DSTATE) return;
    int n = i & 15, d = (i >> 4) & (DINNER - 1), b = i >> 15;
    float h = 0.f;
#pragma unroll
    for (int s = 0; s < NSEG; s++) {
        size_t idx = ((size_t)(b * NSEG + s) * DINNER + d) * DSTATE + n;
        g_hst[idx] = h;
        h = g_P[idx] * h + g_hend[idx];
    }
}

__global__ void __launch_bounds__(128)
scan_pass2(const float* __restrict__ A_log, const float* __restrict__ Dvec,
           const float* __restrict__ Wdt, const float* __restrict__ bdt) {
    __shared__ float sB[CH][16], sC[CH][16];
    __shared__ float sX[CH][CPB], sZ[CH][CPB], sDT[CH][CPB];
    __shared__ float sP[CH][CPB * PSTRIDE];
    const int tid = threadIdx.x;
    const int dd = tid >> 4, n = tid & 15;
    const int q8 = tid & 7;
    const int b = blockIdx.z, seg = blockIdx.y;
    const int d0 = blockIdx.x * CPB;

    const float a  = -__expf(A_log[(d0 + dd) * DSTATE + n]);
    const float wq = Wdt[d0 + q8];
    const float bq = bdt[d0 + q8];
    const float Dq = Dvec[d0 + q8];
    float h = g_hst[((size_t)(b * NSEG + seg) * DINNER + d0 + dd) * DSTATE + n];

    float rdbc[9], rx[2], rz[2], rdt[2];
    auto prefetch = [&](int c) {
        const int tok0 = b * SEQL + seg * SEGTOK + c * CH;
#pragma unroll
        for (int j = 0; j < 9; j++) {
            int i = tid + j * 128;
            if (i < CH * 33) {
                int tt = i / 33, e = i - tt * 33;
                rdbc[j] = g_dbc[(size_t)(tok0 + tt) * 33 + e];
            }
        }
#pragma unroll
        for (int j = 0; j < 2; j++) {
            int tt = (tid + j * 128) >> 3;
            rx[j]  = g_xi[(size_t)(tok0 + tt) * DINNER + d0 + q8];
            rz[j]  = g_xz[(size_t)(tok0 + tt) * (2 * DINNER) + DINNER + d0 + q8];
            rdt[j] = g_dbc[(size_t)(tok0 + tt) * 33];
        }
    };
    auto commit = [&]() {
#pragma unroll
        for (int j = 0; j < 9; j++) {
            int i = tid + j * 128;
            if (i < CH * 33) {
                int tt = i / 33, e = i - tt * 33;
                float v = rdbc[j];
                if (e >= 17)     sC[tt][e - 17] = v;
                else if (e >= 1) sB[tt][e - 1]  = v;
            }
        }
#pragma unroll
        for (int j = 0; j < 2; j++) {
            int tt = (tid + j * 128) >> 3;
            sX[tt][q8] = rx[j];
            sZ[tt][q8] = rz[j];
            float u = rdt[j] * wq + bq;
            sDT[tt][q8] = (u > 20.f) ? u : log1pf(__expf(u));
        }
    };

    prefetch(0);
    for (int c = 0; c < CH_SEG; c++) {
        const int tok0 = b * SEQL + seg * SEGTOK + c * CH;
        commit();
        __syncthreads();
        if (c + 1 < CH_SEG) prefetch(c + 1);

        float dA[CH], bx[CH];
#pragma unroll
        for (int t = 0; t < CH; t++) {
            float dtv = sDT[t][dd];
            dA[t] = __expf(dtv * a);
            bx[t] = (dtv * sB[t][n]) * sX[t][dd];
        }
#pragma unroll
        for (int t = 0; t < CH; t++) {
            h = fmaf(dA[t], h, bx[t]);
            sP[t][dd * PSTRIDE + n] = h * sC[t][n];
        }
        __syncthreads();

        for (int i = tid; i < CH * CPB; i += 128) {
            int tt = i >> 3;
            float s = 0.f;
#pragma unroll
            for (int j = 0; j < 16; j++) s += sP[tt][q8 * PSTRIDE + j];
            float xv = sX[tt][q8], zv = sZ[tt][q8];
            float yv = (s + Dq * xv) * (zv / (1.f + __expf(-zv)));
            g_yh[(size_t)(tok0 + tt) * DINNER + d0 + q8] = __float2half_rn(yv);
        }
        __syncthreads();
    }
}

// ---------------------------------------------------------------------------
extern "C" void kernel_launch(void* const* d_in, const int* in_sizes, int n_in,
                              void* d_out, int out_size) {
    const float* x     = (const float*)d_in[0];
    const float* W_in  = (const float*)d_in[1];
    const float* convw = (const float*)d_in[2];
    const float* convb = (const float*)d_in[3];
    const float* W_x   = (const float*)d_in[4];
    const float* W_dt  = (const float*)d_in[5];
    const float* b_dt  = (const float*)d_in[6];
    const float* A_log = (const float*)d_in[7];
    const float* Dv    = (const float*)d_in[8];
    const float* W_out = (const float*)d_in[9];
    float* out = (float*)d_out;

    float *xz;
    __half *xh, *wh, *woh, *yh;
    cudaGetSymbolAddress((void**)&xz,  g_xz);
    cudaGetSymbolAddress((void**)&xh,  g_xh);
    cudaGetSymbolAddress((void**)&wh,  g_wh);
    cudaGetSymbolAddress((void**)&woh, g_woh);
    cudaGetSymbolAddress((void**)&yh,  g_yh);

    cudaFuncSetAttribute(h_gemm_nt, cudaFuncAttributeMaxDynamicSharedMemorySize, GEMM_SMEM);

    // 0) convert all GEMM operands to fp16 (single launch)
    const int n4tot = N4_X + N4_WI + N4_WO;
    cvt_all_k<<<(n4tot + 255) / 256, 256>>>(x, W_in, W_out);

    // 1) xz = x @ W_in^T   [4096 x 4096], K=1024
    h_gemm_nt<<<dim3(4096 / BN, TOKENS / BM), 256, GEMM_SMEM>>>(xh, wh, xz, TOKENS, 4096, DMODEL);

    // 2) causal depthwise conv + silu -> g_xi
    conv_silu_k<<<(TOKENS * DINNER) / 256, 256>>>(convw, convb);

    // 3) x_dbl = xi @ W_x^T (split-K + deterministic reduce)
    xdbl_part_k<<<dim3(TOKENS / 64, 8), dim3(33, 8)>>>(W_x);
    xdbl_reduce_k<<<(TOKENS * 33 + 255) / 256, 256>>>();

    // 4) segmented selective scan -> g_yh (half)
    scan_pass1<<<dim3(DINNER / CPB, NSEG, 2), 128>>>(A_log, W_dt, b_dt);
    scan_fix_k<<<(2 * DINNER * DSTATE + 255) / 256, 256>>>();
    scan_pass2<<<dim3(DINNER / CPB, NSEG, 2), 128>>>(A_log, Dv, W_dt, b_dt);

    // 5) out = y @ W_out^T   [4096 x 1024], K=2048
    h_gemm_nt<<<dim3(DMODEL / BN, TOKENS / BM), 256, GEMM_SMEM>>>(yh, woh, out, TOKENS, DMODEL, DINNER);
}

// round 12
// speedup vs baseline: 1.2280x; 1.2280x over previous
#include <cuda_runtime.h>
#include <cuda_fp16.h>
#include <math.h>
#include <stdint.h>

#define TOKENS 4096
#define DMODEL 1024
#define DINNER 2048
#define DSTATE 16
#define SEQL   2048

// Scratch (static device globals — no runtime allocation allowed)
__device__ __align__(256) float  g_xz [TOKENS * 2 * DINNER];  // GEMM1 out: xi-preconv | z
__device__ __align__(256) float  g_xi [TOKENS * DINNER];      // conv+silu output (fp32)
__device__ __align__(256) float  g_dbc[TOKENS * 33];
__device__ __align__(256) float  g_dbcp[8][TOKENS * 33];
__device__ __align__(256) __half g_xh [TOKENS * DMODEL];      // half x
__device__ __align__(256) __half g_wh [2 * DINNER * DMODEL];  // half W_in
__device__ __align__(256) __half g_woh[DMODEL * DINNER];      // half W_out
__device__ __align__(256) __half g_yh [TOKENS * DINNER];      // half scan output

// ---------------------------------------------------------------------------
__device__ __forceinline__ void cp_async16(void* smem_dst, const void* gmem_src) {
    uint32_t s = (uint32_t)__cvta_generic_to_shared(smem_dst);
    asm volatile("cp.async.cg.shared.global [%0], [%1], 16;" :: "r"(s), "l"(gmem_src));
}

__device__ __forceinline__ void mma_f16(float* c, const uint32_t* a, const uint32_t* b) {
    asm volatile(
        "mma.sync.aligned.m16n8k16.row.col.f32.f16.f16.f32 "
        "{%0,%1,%2,%3}, {%4,%5,%6,%7}, {%8,%9}, {%0,%1,%2,%3};"
        : "+f"(c[0]), "+f"(c[1]), "+f"(c[2]), "+f"(c[3])
        : "r"(a[0]), "r"(a[1]), "r"(a[2]), "r"(a[3]), "r"(b[0]), "r"(b[1]));
}

__device__ __forceinline__ void ldsm_x4(uint32_t& r0, uint32_t& r1, uint32_t& r2,
                                        uint32_t& r3, uint32_t saddr) {
    asm volatile("ldmatrix.sync.aligned.m8n8.x4.shared.b16 {%0,%1,%2,%3}, [%4];"
        : "=r"(r0), "=r"(r1), "=r"(r2), "=r"(r3) : "r"(saddr));
}

// ---------------------------------------------------------------------------
// FP16 mma.sync GEMM with ldmatrix (unchanged): BM=BN=128, BK=64, 2 CTAs/SM.
// ---------------------------------------------------------------------------
#define BM 128
#define BN 128
#define BK 64
#define STRH 72
#define A_HALFS (BM * STRH)
#define B_HALFS (BN * STRH)
#define STG_HALFS (A_HALFS + B_HALFS)
#define GEMM_SMEM (3 * STG_HALFS * 2)        // 110592 B

__global__ void __launch_bounds__(256, 2)
h_gemm_nt(const __half* __restrict__ A, const __half* __restrict__ B,
          float* __restrict__ C, int M, int N, int K) {
    extern __shared__ __half sh[];
    constexpr int WN = 32;
    constexpr int NFN = 4;
    constexpr int NPAIR = 2;

    const int tid  = threadIdx.x;
    const int wid  = tid >> 5;
    const int lane = tid & 31;
    const int gid  = lane >> 2;
    const int t4   = lane & 3;
    const int wm   = wid & 1;
    const int wn   = wid >> 1;
    const int row0 = blockIdx.y * BM;
    const int col0 = blockIdx.x * BN;

    const uint32_t sbase = (uint32_t)__cvta_generic_to_shared(sh);

    const int a_row  = wm * 64 + (lane & 15);
    const int a_colh = (lane >> 4) * 8;
    const int b_row  = (lane & 7) + ((lane >> 4) * 8);
    const int b_colh = ((lane >> 3) & 1) * 8;

    const int lrow = tid >> 3;
    const int lchk = (tid & 7) * 8;

    float acc[4][NFN][4] = {};
    const int niter = K / BK;

    auto load_stage = [&](int stage, int k0) {
        __half* Sa = sh + stage * STG_HALFS;
        __half* Sb = Sa + A_HALFS;
#pragma unroll
        for (int i = 0; i < BM / 32; i++) {
            int r = lrow + i * 32;
            cp_async16(&Sa[r * STRH + lchk], A + (size_t)(row0 + r) * K + k0 + lchk);
        }
#pragma unroll
        for (int i = 0; i < BN / 32; i++) {
            int r = lrow + i * 32;
            cp_async16(&Sb[r * STRH + lchk], B + (size_t)(col0 + r) * K + k0 + lchk);
        }
    };

    load_stage(0, 0);
    asm volatile("cp.async.commit_group;");
    if (niter > 1) load_stage(1, BK);
    asm volatile("cp.async.commit_group;");

    int s = 0;
    for (int it = 0; it < niter; it++) {
        asm volatile("cp.async.wait_group 1;");
        __syncthreads();

        if (it + 2 < niter) load_stage((it + 2) % 3, (it + 2) * BK);
        asm volatile("cp.async.commit_group;");

        const uint32_t sA = sbase + (uint32_t)(s * STG_HALFS) * 2;
        const uint32_t sB = sA + A_HALFS * 2;
#pragma unroll
        for (int kk = 0; kk < BK / 16; kk++) {
            const int kb = kk * 16;
            uint32_t af[4][4], bf[NFN][2];
#pragma unroll
            for (int fm = 0; fm < 4; fm++)
                ldsm_x4(af[fm][0], af[fm][1], af[fm][2], af[fm][3],
                        sA + (uint32_t)((a_row + fm * 16) * STRH + kb + a_colh) * 2);
#pragma unroll
            for (int p = 0; p < NPAIR; p++)
                ldsm_x4(bf[2 * p][0], bf[2 * p][1], bf[2 * p + 1][0], bf[2 * p + 1][1],
                        sB + (uint32_t)((wn * WN + p * 16 + b_row) * STRH + kb + b_colh) * 2);
#pragma unroll
            for (int fm = 0; fm < 4; fm++)
#pragma unroll
                for (int fn = 0; fn < NFN; fn++)
                    mma_f16(acc[fm][fn], af[fm], bf[fn]);
        }
        __syncthreads();
        s = (s + 1) % 3;
    }

#pragma unroll
    for (int fm = 0; fm < 4; fm++) {
        int r = row0 + wm * 64 + fm * 16 + gid;
#pragma unroll
        for (int fn = 0; fn < NFN; fn++) {
            int cbase = col0 + wn * WN + fn * 8 + t4 * 2;
            float2* p0 = (float2*)&C[(size_t)r * N + cbase];
            float2* p1 = (float2*)&C[(size_t)(r + 8) * N + cbase];
            *p0 = make_float2(acc[fm][fn][0], acc[fm][fn][1]);
            *p1 = make_float2(acc[fm][fn][2], acc[fm][fn][3]);
        }
    }
}

// ---------------------------------------------------------------------------
// fp32->fp16 conversion, split into two launches (x+W_in, then W_out) so the
// fused xdbl_conv kernel lands in the profiled 4th launch slot.
// ---------------------------------------------------------------------------
#define N4_X  (TOKENS * DMODEL / 4)
#define N4_WI (2 * DINNER * DMODEL / 4)
#define N4_WO (DMODEL * DINNER / 4)

__global__ void cvt_xw_k(const float* __restrict__ x, const float* __restrict__ Wi) {
    int i = blockIdx.x * blockDim.x + threadIdx.x;
    const float* src; __half* dst; int off;
    if (i < N4_X)               { src = x;  dst = g_xh; off = i; }
    else if (i < N4_X + N4_WI)  { src = Wi; dst = g_wh; off = i - N4_X; }
    else return;
    float4 v = ((const float4*)src)[off];
    __half2 h0 = __float22half2_rn(make_float2(v.x, v.y));
    __half2 h1 = __float22half2_rn(make_float2(v.z, v.w));
    ((uint2*)dst)[off] = make_uint2(*(uint32_t*)&h0, *(uint32_t*)&h1);
}

__global__ void cvt_wo_k(const float* __restrict__ Wo) {
    int i = blockIdx.x * blockDim.x + threadIdx.x;
    if (i >= N4_WO) return;
    float4 v = ((const float4*)Wo)[i];
    __half2 h0 = __float22half2_rn(make_float2(v.x, v.y));
    __half2 h1 = __float22half2_rn(make_float2(v.z, v.w));
    ((uint2*)g_woh)[i] = make_uint2(*(uint32_t*)&h0, *(uint32_t*)&h1);
}

// ---------------------------------------------------------------------------
// Fused conv+SiLU + x_dbl split-K partials.
// grid (TOKENS/64, 8), block (33,8). Each block: 64 tokens x 256 channels.
// Per 32-channel chunk: stage xz tile (+3 halo rows, zeroed at batch start,
// which reproduces the causal l>=D masking exactly), compute xi = silu(conv)
// into smem AND g_xi (single write, coalesced), then accumulate the 33-wide
// projection. Same fma order as the old conv kernel -> numerically identical.
// ---------------------------------------------------------------------------
__global__ void xdbl_conv_k(const float* __restrict__ Wx,
                            const float* __restrict__ cw,
                            const float* __restrict__ cb) {
    __shared__ float Sxz[67][36];    // [halo+token][channel], conflict-free both phases
    __shared__ float Xs [64][33];    // xi tile, stores conflict-free, reads broadcast
    __shared__ float Ws [33][33];
    __shared__ float Scw[32][5];     // w0..w3, bias per channel
    const int tx = threadIdx.x, ty = threadIdx.y;   // (33,8)
    const int tid = ty * 33 + tx;                   // 0..263
    const int tok0 = blockIdx.x * 64;
    const int kbase = blockIdx.y * 256;
    const bool halo_ok = (tok0 & (SEQL - 1)) != 0;  // false at batch starts

    float acc[8] = {};

    for (int kc = 0; kc < 8; kc++) {
        const int k0 = kbase + kc * 32;
        // stage Wx slice
        for (int i = tid; i < 33 * 32; i += 264) {
            int e = i >> 5, kk = i & 31;
            Ws[e][kk] = Wx[(size_t)e * DINNER + k0 + kk];
        }
        // stage conv weights + bias
        if (tid < 32 * 5) {
            int kk = tid / 5, j = tid - kk * 5;
            Scw[kk][j] = (j < 4) ? cw[(k0 + kk) * 4 + j] : cb[k0 + kk];
        }
        // stage xz tile with 3 halo rows (float4, coalesced)
        for (int i = tid; i < 67 * 8; i += 264) {
            int row = i >> 3, c4 = (i & 7) * 4;
            float4 v = make_float4(0.f, 0.f, 0.f, 0.f);
            if (row >= 3 || halo_ok)
                v = *(const float4*)&g_xz[(size_t)(tok0 - 3 + row) * (2 * DINNER) + k0 + c4];
            *(float4*)&Sxz[row][c4] = v;
        }
        __syncthreads();

        // conv + silu -> Xs and g_xi
        for (int i = tid; i < 64 * 32; i += 264) {
            int tt = i >> 5, kk = i & 31;
            float a0 = Scw[kk][4];
            a0 = fmaf(Sxz[tt + 0][kk], Scw[kk][0], a0);
            a0 = fmaf(Sxz[tt + 1][kk], Scw[kk][1], a0);
            a0 = fmaf(Sxz[tt + 2][kk], Scw[kk][2], a0);
            a0 = fmaf(Sxz[tt + 3][kk], Scw[kk][3], a0);
            float xv = a0 / (1.f + __expf(-a0));
            Xs[tt][kk] = xv;
            g_xi[(size_t)(tok0 + tt) * DINNER + k0 + kk] = xv;
        }
        __syncthreads();

        // projection accumulate (Xs reads broadcast across the 33 tx lanes)
#pragma unroll
        for (int kk = 0; kk < 32; kk++) {
            float w = Ws[tx][kk];
#pragma unroll
            for (int i = 0; i < 8; i++)
                acc[i] = fmaf(Xs[ty * 8 + i][kk], w, acc[i]);
        }
        __syncthreads();
    }
#pragma unroll
    for (int i = 0; i < 8; i++)
        g_dbcp[blockIdx.y][(size_t)(tok0 + ty * 8 + i) * 33 + tx] = acc[i];
}

__global__ void xdbl_reduce_k() {
    int i = blockIdx.x * blockDim.x + threadIdx.x;
    if (i >= TOKENS * 33) return;
    float s = 0.f;
#pragma unroll
    for (int p = 0; p < 8; p++) s += g_dbcp[p][i];
    g_dbc[i] = s;
}

// ---------------------------------------------------------------------------
// Selective scan (R10 version: monolithic, cross-chunk register prefetch)
// ---------------------------------------------------------------------------
#define CH 32
#define CPB 8
#define PSTRIDE 17
#define NCHUNK (SEQL / CH)

__global__ void __launch_bounds__(128, 4)
scan_k(const float* __restrict__ A_log, const float* __restrict__ Dvec,
       const float* __restrict__ Wdt, const float* __restrict__ bdt) {
    __shared__ float sB[CH][16], sC[CH][16];
    __shared__ float sX[CH][CPB], sZ[CH][CPB], sDT[CH][CPB];
    __shared__ float sP[CH][CPB * PSTRIDE];
    const int tid = threadIdx.x;              // 128
    const int dd = tid >> 4, n = tid & 15;
    const int q8 = tid & 7;
    const int b = blockIdx.y;
    const int d0 = blockIdx.x * CPB;

    const float a  = -__expf(A_log[(d0 + dd) * DSTATE + n]);
    const float wq = Wdt[d0 + q8];
    const float bq = bdt[d0 + q8];
    const float Dq = Dvec[d0 + q8];
    float h = 0.f;

    float rdbc[9], rx[2], rz[2], rdt[2];

    auto prefetch = [&](int c) {
        const int tok0 = b * SEQL + c * CH;
#pragma unroll
        for (int j = 0; j < 9; j++) {
            int i = tid + j * 128;
            if (i < CH * 33) {
                int tt = i / 33, e = i - tt * 33;
                rdbc[j] = g_dbc[(size_t)(tok0 + tt) * 33 + e];
            }
        }
#pragma unroll
        for (int j = 0; j < 2; j++) {
            int tt = (tid + j * 128) >> 3;
            rx[j]  = g_xi[(size_t)(tok0 + tt) * DINNER + d0 + q8];
            rz[j]  = g_xz[(size_t)(tok0 + tt) * (2 * DINNER) + DINNER + d0 + q8];
            rdt[j] = g_dbc[(size_t)(tok0 + tt) * 33];
        }
    };
    auto commit = [&]() {
#pragma unroll
        for (int j = 0; j < 9; j++) {
            int i = tid + j * 128;
            if (i < CH * 33) {
                int tt = i / 33, e = i - tt * 33;
                float v = rdbc[j];
                if (e >= 17)     sC[tt][e - 17] = v;
                else if (e >= 1) sB[tt][e - 1]  = v;
            }
        }
#pragma unroll
        for (int j = 0; j < 2; j++) {
            int tt = (tid + j * 128) >> 3;
            sX[tt][q8] = rx[j];
            sZ[tt][q8] = rz[j];
            float u = rdt[j] * wq + bq;
            sDT[tt][q8] = (u > 20.f) ? u : log1pf(__expf(u));
        }
    };

    prefetch(0);
    for (int c = 0; c < NCHUNK; c++) {
        const int tok0 = b * SEQL + c * CH;
        commit();
        __syncthreads();
        if (c + 1 < NCHUNK) prefetch(c + 1);

        float dA[CH], bx[CH];
#pragma unroll
        for (int t = 0; t < CH; t++) {
            float dtv = sDT[t][dd];
            dA[t] = __expf(dtv * a);
            bx[t] = (dtv * sB[t][n]) * sX[t][dd];
        }
#pragma unroll
        for (int t = 0; t < CH; t++) {
            h = fmaf(dA[t], h, bx[t]);
            sP[t][dd * PSTRIDE + n] = h * sC[t][n];
        }
        __syncthreads();

        for (int i = tid; i < CH * CPB; i += 128) {
            int tt = i >> 3;
            float s = 0.f;
#pragma unroll
            for (int j = 0; j < 16; j++) s += sP[tt][q8 * PSTRIDE + j];
            float xv = sX[tt][q8], zv = sZ[tt][q8];
            float yv = (s + Dq * xv) * (zv / (1.f + __expf(-zv)));
            g_yh[(size_t)(tok0 + tt) * DINNER + d0 + q8] = __float2half_rn(yv);
        }
        __syncthreads();
    }
}

// ---------------------------------------------------------------------------
extern "C" void kernel_launch(void* const* d_in, const int* in_sizes, int n_in,
                              void* d_out, int out_size) {
    const float* x     = (const float*)d_in[0];
    const float* W_in  = (const float*)d_in[1];
    const float* convw = (const float*)d_in[2];
    const float* convb = (const float*)d_in[3];
    const float* W_x   = (const float*)d_in[4];
    const float* W_dt  = (const float*)d_in[5];
    const float* b_dt  = (const float*)d_in[6];
    const float* A_log = (const float*)d_in[7];
    const float* Dv    = (const float*)d_in[8];
    const float* W_out = (const float*)d_in[9];
    float* out = (float*)d_out;

    float *xz;
    __half *xh, *wh, *woh, *yh;
    cudaGetSymbolAddress((void**)&xz,  g_xz);
    cudaGetSymbolAddress((void**)&xh,  g_xh);
    cudaGetSymbolAddress((void**)&wh,  g_wh);
    cudaGetSymbolAddress((void**)&woh, g_woh);
    cudaGetSymbolAddress((void**)&yh,  g_yh);

    cudaFuncSetAttribute(h_gemm_nt, cudaFuncAttributeMaxDynamicSharedMemorySize, GEMM_SMEM);

    // 1-2) convert GEMM operands to fp16 (two launches; keeps fused kernel 4th)
    cvt_xw_k<<<(N4_X + N4_WI + 255) / 256, 256>>>(x, W_in);
    cvt_wo_k<<<(N4_WO + 255) / 256, 256>>>(W_out);

    // 3) xz = x @ W_in^T   [4096 x 4096], K=1024
    h_gemm_nt<<<dim3(4096 / BN, TOKENS / BM), 256, GEMM_SMEM>>>(xh, wh, xz, TOKENS, 4096, DMODEL);

    // 4) fused conv+silu + x_dbl partials  [profiled slot]
    xdbl_conv_k<<<dim3(TOKENS / 64, 8), dim3(33, 8)>>>(W_x, convw, convb);

    // 5) deterministic split-K reduce
    xdbl_reduce_k<<<(TOKENS * 33 + 255) / 256, 256>>>();

    // 6) selective scan -> g_yh (half)
    scan_k<<<dim3(DINNER / CPB, 2), 128>>>(A_log, Dv, W_dt, b_dt);

    // 7) out = y @ W_out^T   [4096 x 1024], K=2048
    h_gemm_nt<<<dim3(DMODEL / BN, TOKENS / BM), 256, GEMM_SMEM>>>(yh, woh, out, TOKENS, DMODEL, DINNER);
}

// round 13
// speedup vs baseline: 1.4903x; 1.2136x over previous
#include <cuda_runtime.h>
#include <cuda_fp16.h>
#include <math.h>
#include <stdint.h>

#define TOKENS 4096
#define DMODEL 1024
#define DINNER 2048
#define DSTATE 16
#define SEQL   2048

// Scratch (static device globals — no runtime allocation allowed)
__device__ __align__(256) float  g_xz [TOKENS * 2 * DINNER];  // GEMM1 out: xi-preconv | z
__device__ __align__(256) float  g_xi [TOKENS * DINNER];      // conv+silu output (fp32)
__device__ __align__(256) float  g_dbc[TOKENS * 33];
__device__ __align__(256) float  g_dbcp[16][TOKENS * 33];
__device__ __align__(256) __half g_xh [TOKENS * DMODEL];      // half x
__device__ __align__(256) __half g_wh [2 * DINNER * DMODEL];  // half W_in
__device__ __align__(256) __half g_woh[DMODEL * DINNER];      // half W_out
__device__ __align__(256) __half g_yh [TOKENS * DINNER];      // half scan output

// ---------------------------------------------------------------------------
__device__ __forceinline__ void cp_async16(void* smem_dst, const void* gmem_src) {
    uint32_t s = (uint32_t)__cvta_generic_to_shared(smem_dst);
    asm volatile("cp.async.cg.shared.global [%0], [%1], 16;" :: "r"(s), "l"(gmem_src));
}

__device__ __forceinline__ void mma_f16(float* c, const uint32_t* a, const uint32_t* b) {
    asm volatile(
        "mma.sync.aligned.m16n8k16.row.col.f32.f16.f16.f32 "
        "{%0,%1,%2,%3}, {%4,%5,%6,%7}, {%8,%9}, {%0,%1,%2,%3};"
        : "+f"(c[0]), "+f"(c[1]), "+f"(c[2]), "+f"(c[3])
        : "r"(a[0]), "r"(a[1]), "r"(a[2]), "r"(a[3]), "r"(b[0]), "r"(b[1]));
}

__device__ __forceinline__ void ldsm_x4(uint32_t& r0, uint32_t& r1, uint32_t& r2,
                                        uint32_t& r3, uint32_t saddr) {
    asm volatile("ldmatrix.sync.aligned.m8n8.x4.shared.b16 {%0,%1,%2,%3}, [%4];"
        : "=r"(r0), "=r"(r1), "=r"(r2), "=r"(r3) : "r"(saddr));
}

// ---------------------------------------------------------------------------
// FP16 mma.sync GEMM with ldmatrix (unchanged): BM=BN=128, BK=64, 2 CTAs/SM.
// ---------------------------------------------------------------------------
#define BM 128
#define BN 128
#define BK 64
#define STRH 72
#define A_HALFS (BM * STRH)
#define B_HALFS (BN * STRH)
#define STG_HALFS (A_HALFS + B_HALFS)
#define GEMM_SMEM (3 * STG_HALFS * 2)        // 110592 B

__global__ void __launch_bounds__(256, 2)
h_gemm_nt(const __half* __restrict__ A, const __half* __restrict__ B,
          float* __restrict__ C, int M, int N, int K) {
    extern __shared__ __half sh[];
    constexpr int WN = 32;
    constexpr int NFN = 4;
    constexpr int NPAIR = 2;

    const int tid  = threadIdx.x;
    const int wid  = tid >> 5;
    const int lane = tid & 31;
    const int gid  = lane >> 2;
    const int t4   = lane & 3;
    const int wm   = wid & 1;
    const int wn   = wid >> 1;
    const int row0 = blockIdx.y * BM;
    const int col0 = blockIdx.x * BN;

    const uint32_t sbase = (uint32_t)__cvta_generic_to_shared(sh);

    const int a_row  = wm * 64 + (lane & 15);
    const int a_colh = (lane >> 4) * 8;
    const int b_row  = (lane & 7) + ((lane >> 4) * 8);
    const int b_colh = ((lane >> 3) & 1) * 8;

    const int lrow = tid >> 3;
    const int lchk = (tid & 7) * 8;

    float acc[4][NFN][4] = {};
    const int niter = K / BK;

    auto load_stage = [&](int stage, int k0) {
        __half* Sa = sh + stage * STG_HALFS;
        __half* Sb = Sa + A_HALFS;
#pragma unroll
        for (int i = 0; i < BM / 32; i++) {
            int r = lrow + i * 32;
            cp_async16(&Sa[r * STRH + lchk], A + (size_t)(row0 + r) * K + k0 + lchk);
        }
#pragma unroll
        for (int i = 0; i < BN / 32; i++) {
            int r = lrow + i * 32;
            cp_async16(&Sb[r * STRH + lchk], B + (size_t)(col0 + r) * K + k0 + lchk);
        }
    };

    load_stage(0, 0);
    asm volatile("cp.async.commit_group;");
    if (niter > 1) load_stage(1, BK);
    asm volatile("cp.async.commit_group;");

    int s = 0;
    for (int it = 0; it < niter; it++) {
        asm volatile("cp.async.wait_group 1;");
        __syncthreads();

        if (it + 2 < niter) load_stage((it + 2) % 3, (it + 2) * BK);
        asm volatile("cp.async.commit_group;");

        const uint32_t sA = sbase + (uint32_t)(s * STG_HALFS) * 2;
        const uint32_t sB = sA + A_HALFS * 2;
#pragma unroll
        for (int kk = 0; kk < BK / 16; kk++) {
            const int kb = kk * 16;
            uint32_t af[4][4], bf[NFN][2];
#pragma unroll
            for (int fm = 0; fm < 4; fm++)
                ldsm_x4(af[fm][0], af[fm][1], af[fm][2], af[fm][3],
                        sA + (uint32_t)((a_row + fm * 16) * STRH + kb + a_colh) * 2);
#pragma unroll
            for (int p = 0; p < NPAIR; p++)
                ldsm_x4(bf[2 * p][0], bf[2 * p][1], bf[2 * p + 1][0], bf[2 * p + 1][1],
                        sB + (uint32_t)((wn * WN + p * 16 + b_row) * STRH + kb + b_colh) * 2);
#pragma unroll
            for (int fm = 0; fm < 4; fm++)
#pragma unroll
                for (int fn = 0; fn < NFN; fn++)
                    mma_f16(acc[fm][fn], af[fm], bf[fn]);
        }
        __syncthreads();
        s = (s + 1) % 3;
    }

#pragma unroll
    for (int fm = 0; fm < 4; fm++) {
        int r = row0 + wm * 64 + fm * 16 + gid;
#pragma unroll
        for (int fn = 0; fn < NFN; fn++) {
            int cbase = col0 + wn * WN + fn * 8 + t4 * 2;
            float2* p0 = (float2*)&C[(size_t)r * N + cbase];
            float2* p1 = (float2*)&C[(size_t)(r + 8) * N + cbase];
            *p0 = make_float2(acc[fm][fn][0], acc[fm][fn][1]);
            *p1 = make_float2(acc[fm][fn][2], acc[fm][fn][3]);
        }
    }
}

// ---------------------------------------------------------------------------
// fp32->fp16 conversion (split keeps xdbl_conv in profiled 4th launch slot)
// ---------------------------------------------------------------------------
#define N4_X  (TOKENS * DMODEL / 4)
#define N4_WI (2 * DINNER * DMODEL / 4)
#define N4_WO (DMODEL * DINNER / 4)

__global__ void cvt_xw_k(const float* __restrict__ x, const float* __restrict__ Wi) {
    int i = blockIdx.x * blockDim.x + threadIdx.x;
    const float* src; __half* dst; int off;
    if (i < N4_X)               { src = x;  dst = g_xh; off = i; }
    else if (i < N4_X + N4_WI)  { src = Wi; dst = g_wh; off = i - N4_X; }
    else return;
    float4 v = ((const float4*)src)[off];
    __half2 h0 = __float22half2_rn(make_float2(v.x, v.y));
    __half2 h1 = __float22half2_rn(make_float2(v.z, v.w));
    ((uint2*)dst)[off] = make_uint2(*(uint32_t*)&h0, *(uint32_t*)&h1);
}

__global__ void cvt_wo_k(const float* __restrict__ Wo) {
    int i = blockIdx.x * blockDim.x + threadIdx.x;
    if (i >= N4_WO) return;
    float4 v = ((const float4*)Wo)[i];
    __half2 h0 = __float22half2_rn(make_float2(v.x, v.y));
    __half2 h1 = __float22half2_rn(make_float2(v.z, v.w));
    ((uint2*)g_woh)[i] = make_uint2(*(uint32_t*)&h0, *(uint32_t*)&h1);
}

// ---------------------------------------------------------------------------
// Fused conv+SiLU + x_dbl partials, split-K 16 (grid 64x16 = 1024 CTAs,
// fixes the measured grid-limited occupancy 45.6%).
// ---------------------------------------------------------------------------
__global__ void xdbl_conv_k(const float* __restrict__ Wx,
                            const float* __restrict__ cw,
                            const float* __restrict__ cb) {
    __shared__ float Sxz[67][36];
    __shared__ float Xs [64][33];
    __shared__ float Ws [33][33];
    __shared__ float Scw[32][5];
    const int tx = threadIdx.x, ty = threadIdx.y;   // (33,8)
    const int tid = ty * 33 + tx;
    const int tok0 = blockIdx.x * 64;
    const int kbase = blockIdx.y * 128;             // split-K 16
    const bool halo_ok = (tok0 & (SEQL - 1)) != 0;

    float acc[8] = {};

    for (int kc = 0; kc < 4; kc++) {
        const int k0 = kbase + kc * 32;
        for (int i = tid; i < 33 * 32; i += 264) {
            int e = i >> 5, kk = i & 31;
            Ws[e][kk] = Wx[(size_t)e * DINNER + k0 + kk];
        }
        if (tid < 32 * 5) {
            int kk = tid / 5, j = tid - kk * 5;
            Scw[kk][j] = (j < 4) ? cw[(k0 + kk) * 4 + j] : cb[k0 + kk];
        }
        for (int i = tid; i < 67 * 8; i += 264) {
            int row = i >> 3, c4 = (i & 7) * 4;
            float4 v = make_float4(0.f, 0.f, 0.f, 0.f);
            if (row >= 3 || halo_ok)
                v = *(const float4*)&g_xz[(size_t)(tok0 - 3 + row) * (2 * DINNER) + k0 + c4];
            *(float4*)&Sxz[row][c4] = v;
        }
        __syncthreads();

        for (int i = tid; i < 64 * 32; i += 264) {
            int tt = i >> 5, kk = i & 31;
            float a0 = Scw[kk][4];
            a0 = fmaf(Sxz[tt + 0][kk], Scw[kk][0], a0);
            a0 = fmaf(Sxz[tt + 1][kk], Scw[kk][1], a0);
            a0 = fmaf(Sxz[tt + 2][kk], Scw[kk][2], a0);
            a0 = fmaf(Sxz[tt + 3][kk], Scw[kk][3], a0);
            float xv = a0 / (1.f + __expf(-a0));
            Xs[tt][kk] = xv;
            g_xi[(size_t)(tok0 + tt) * DINNER + k0 + kk] = xv;
        }
        __syncthreads();

#pragma unroll
        for (int kk = 0; kk < 32; kk++) {
            float w = Ws[tx][kk];
#pragma unroll
            for (int i = 0; i < 8; i++)
                acc[i] = fmaf(Xs[ty * 8 + i][kk], w, acc[i]);
        }
        __syncthreads();
    }
#pragma unroll
    for (int i = 0; i < 8; i++)
        g_dbcp[blockIdx.y][(size_t)(tok0 + ty * 8 + i) * 33 + tx] = acc[i];
}

__global__ void xdbl_reduce_k() {
    int i = blockIdx.x * blockDim.x + threadIdx.x;
    if (i >= TOKENS * 33) return;
    float s = 0.f;
#pragma unroll
    for (int p = 0; p < 16; p++) s += g_dbcp[p][i];
    g_dbc[i] = s;
}

// ---------------------------------------------------------------------------
// Selective scan with cp.async double-buffered staging.
// dbc chunk slice is 4224 contiguous bytes -> 3 cp.async16/thread replaces
// the register-prefetch machinery; (softplus(dt), xi) packed into float2 so
// loop A issues one LDS.64. Arithmetic identical to R12.
// ---------------------------------------------------------------------------
#define CH 32
#define CPB 8
#define PSTRIDE 17
#define NCHUNK (SEQL / CH)

__global__ void __launch_bounds__(128, 4)
scan_k(const float* __restrict__ A_log, const float* __restrict__ Dvec,
       const float* __restrict__ Wdt, const float* __restrict__ bdt) {
    __shared__ __align__(16) float  sDBC[2][CH * 33];
    __shared__ __align__(16) float  sXr [2][CH][8];
    __shared__ __align__(16) float  sZ  [2][CH][8];
    __shared__ __align__(16) float2 sDX [2][CH][8];   // (softplus(dt), xi)
    __shared__ float sP[CH][CPB * PSTRIDE];
    const int tid = threadIdx.x;              // 128
    const int dd = tid >> 4, n = tid & 15;
    const int q8 = tid & 7;
    const int b = blockIdx.y;
    const int d0 = blockIdx.x * CPB;

    const float a  = -__expf(A_log[(d0 + dd) * DSTATE + n]);
    const float wq = Wdt[d0 + q8];
    const float bq = bdt[d0 + q8];
    const float Dq = Dvec[d0 + q8];
    float h = 0.f;

    auto issue = [&](int c) {
        const int buf = c & 1;
        const int tok0 = b * SEQL + c * CH;
        const float* src = &g_dbc[(size_t)tok0 * 33];   // 4224B contiguous
#pragma unroll
        for (int j = 0; j < 3; j++) {
            int g = tid + j * 128;
            if (g < 264) cp_async16(&sDBC[buf][g * 4], src + g * 4);
        }
        if (tid < 64) {
            int token = tid >> 1, half = tid & 1;
            cp_async16(&sXr[buf][token][half * 4],
                       &g_xi[(size_t)(tok0 + token) * DINNER + d0 + half * 4]);
        } else {
            int t2 = tid - 64, token = t2 >> 1, half = t2 & 1;
            cp_async16(&sZ[buf][token][half * 4],
                       &g_xz[(size_t)(tok0 + token) * (2 * DINNER) + DINNER + d0 + half * 4]);
        }
        asm volatile("cp.async.commit_group;");
    };

    issue(0);
    for (int c = 0; c < NCHUNK; c++) {
        const int buf = c & 1;
        const int tok0 = b * SEQL + c * CH;
        asm volatile("cp.async.wait_group 0;");
        __syncthreads();                       // chunk c data visible block-wide

        // pack (softplus(dt), xi) per (token, q8)
#pragma unroll
        for (int j = 0; j < 2; j++) {
            int tt = (tid + j * 128) >> 3;
            float u = sDBC[buf][tt * 33] * wq + bq;
            float sp = (u > 20.f) ? u : log1pf(__expf(u));
            sDX[buf][tt][q8] = make_float2(sp, sXr[buf][tt][q8]);
        }
        if (c + 1 < NCHUNK) issue(c + 1);      // overlaps loops + output below
        __syncthreads();                       // sDX visible

        float dA[CH], bx[CH];
#pragma unroll
        for (int t = 0; t < CH; t++) {
            float2 dx = sDX[buf][t][dd];
            dA[t] = __expf(dx.x * a);
            bx[t] = (dx.x * sDBC[buf][t * 33 + 1 + n]) * dx.y;
        }
#pragma unroll
        for (int t = 0; t < CH; t++) {
            h = fmaf(dA[t], h, bx[t]);
            sP[t][dd * PSTRIDE + n] = h * sDBC[buf][t * 33 + 17 + n];
        }
        __syncthreads();                       // sP visible

#pragma unroll
        for (int j = 0; j < 2; j++) {
            int i = tid + j * 128;
            int tt = i >> 3;
            float s = 0.f;
#pragma unroll
            for (int k = 0; k < 16; k++) s += sP[tt][q8 * PSTRIDE + k];
            float xv = sXr[buf][tt][q8], zv = sZ[buf][tt][q8];
            float yv = (s + Dq * xv) * (zv / (1.f + __expf(-zv)));
            g_yh[(size_t)(tok0 + tt) * DINNER + d0 + q8] = __float2half_rn(yv);
        }
        // next iteration's wait_group + syncthreads protects sP reuse
    }
}

// ---------------------------------------------------------------------------
extern "C" void kernel_launch(void* const* d_in, const int* in_sizes, int n_in,
                              void* d_out, int out_size) {
    const float* x     = (const float*)d_in[0];
    const float* W_in  = (const float*)d_in[1];
    const float* convw = (const float*)d_in[2];
    const float* convb = (const float*)d_in[3];
    const float* W_x   = (const float*)d_in[4];
    const float* W_dt  = (const float*)d_in[5];
    const float* b_dt  = (const float*)d_in[6];
    const float* A_log = (const float*)d_in[7];
    const float* Dv    = (const float*)d_in[8];
    const float* W_out = (const float*)d_in[9];
    float* out = (float*)d_out;

    float *xz;
    __half *xh, *wh, *woh, *yh;
    cudaGetSymbolAddress((void**)&xz,  g_xz);
    cudaGetSymbolAddress((void**)&xh,  g_xh);
    cudaGetSymbolAddress((void**)&wh,  g_wh);
    cudaGetSymbolAddress((void**)&woh, g_woh);
    cudaGetSymbolAddress((void**)&yh,  g_yh);

    cudaFuncSetAttribute(h_gemm_nt, cudaFuncAttributeMaxDynamicSharedMemorySize, GEMM_SMEM);

    // 1-2) convert GEMM operands to fp16
    cvt_xw_k<<<(N4_X + N4_WI + 255) / 256, 256>>>(x, W_in);
    cvt_wo_k<<<(N4_WO + 255) / 256, 256>>>(W_out);

    // 3) xz = x @ W_in^T   [4096 x 4096], K=1024
    h_gemm_nt<<<dim3(4096 / BN, TOKENS / BM), 256, GEMM_SMEM>>>(xh, wh, xz, TOKENS, 4096, DMODEL);

    // 4) fused conv+silu + x_dbl partials (split-K 16)  [profiled slot]
    xdbl_conv_k<<<dim3(TOKENS / 64, 16), dim3(33, 8)>>>(W_x, convw, convb);

    // 5) deterministic split-K reduce
    xdbl_reduce_k<<<(TOKENS * 33 + 255) / 256, 256>>>();

    // 6) selective scan -> g_yh (half)
    scan_k<<<dim3(DINNER / CPB, 2), 128>>>(A_log, Dv, W_dt, b_dt);

    // 7) out = y @ W_out^T   [4096 x 1024], K=2048
    h_gemm_nt<<<dim3(DMODEL / BN, TOKENS / BM), 256, GEMM_SMEM>>>(yh, woh, out, TOKENS, DMODEL, DINNER);
}

// round 14
// speedup vs baseline: 1.4948x; 1.0030x over previous
#include <cuda_runtime.h>
#include <cuda_fp16.h>
#include <math.h>
#include <stdint.h>

#define TOKENS 4096
#define DMODEL 1024
#define DINNER 2048
#define DSTATE 16
#define SEQL   2048

// Scratch (static device globals — no runtime allocation allowed)
__device__ __align__(256) float  g_xz [TOKENS * 2 * DINNER];  // GEMM1 out: xi-preconv | z
__device__ __align__(256) float  g_xi [TOKENS * DINNER];      // conv+silu output (fp32)
__device__ __align__(256) float  g_dbc[TOKENS * 33];
__device__ __align__(256) float  g_dbcp[16][TOKENS * 33];
__device__ __align__(256) __half g_xh [TOKENS * DMODEL];      // half x
__device__ __align__(256) __half g_wh [2 * DINNER * DMODEL];  // half W_in
__device__ __align__(256) __half g_woh[DMODEL * DINNER];      // half W_out
__device__ __align__(256) __half g_yh [TOKENS * DINNER];      // half scan output

// ---------------------------------------------------------------------------
__device__ __forceinline__ void cp_async16(void* smem_dst, const void* gmem_src) {
    uint32_t s = (uint32_t)__cvta_generic_to_shared(smem_dst);
    asm volatile("cp.async.cg.shared.global [%0], [%1], 16;" :: "r"(s), "l"(gmem_src));
}

__device__ __forceinline__ void mma_f16(float* c, const uint32_t* a, const uint32_t* b) {
    asm volatile(
        "mma.sync.aligned.m16n8k16.row.col.f32.f16.f16.f32 "
        "{%0,%1,%2,%3}, {%4,%5,%6,%7}, {%8,%9}, {%0,%1,%2,%3};"
        : "+f"(c[0]), "+f"(c[1]), "+f"(c[2]), "+f"(c[3])
        : "r"(a[0]), "r"(a[1]), "r"(a[2]), "r"(a[3]), "r"(b[0]), "r"(b[1]));
}

__device__ __forceinline__ void ldsm_x4(uint32_t& r0, uint32_t& r1, uint32_t& r2,
                                        uint32_t& r3, uint32_t saddr) {
    asm volatile("ldmatrix.sync.aligned.m8n8.x4.shared.b16 {%0,%1,%2,%3}, [%4];"
        : "=r"(r0), "=r"(r1), "=r"(r2), "=r"(r3) : "r"(saddr));
}

// ---------------------------------------------------------------------------
// FP16 mma.sync GEMM. BM=BN=128, BK=64, 3-stage cp.async, 2 CTAs/SM.
// Single barrier per iter: at iter it, loads fill stage (it+2)%3 ≡ (it-1)%3,
// which all warps finished reading before arriving at this iter's barrier.
// ---------------------------------------------------------------------------
#define BM 128
#define BN 128
#define BK 64
#define STRH 72
#define A_HALFS (BM * STRH)
#define B_HALFS (BN * STRH)
#define STG_HALFS (A_HALFS + B_HALFS)
#define GEMM_SMEM (3 * STG_HALFS * 2)        // 110592 B

__global__ void __launch_bounds__(256, 2)
h_gemm_nt(const __half* __restrict__ A, const __half* __restrict__ B,
          float* __restrict__ C, int M, int N, int K) {
    extern __shared__ __half sh[];
    constexpr int WN = 32;
    constexpr int NFN = 4;
    constexpr int NPAIR = 2;

    const int tid  = threadIdx.x;
    const int wid  = tid >> 5;
    const int lane = tid & 31;
    const int gid  = lane >> 2;
    const int t4   = lane & 3;
    const int wm   = wid & 1;
    const int wn   = wid >> 1;
    const int row0 = blockIdx.y * BM;
    const int col0 = blockIdx.x * BN;

    const uint32_t sbase = (uint32_t)__cvta_generic_to_shared(sh);

    const int a_row  = wm * 64 + (lane & 15);
    const int a_colh = (lane >> 4) * 8;
    const int b_row  = (lane & 7) + ((lane >> 4) * 8);
    const int b_colh = ((lane >> 3) & 1) * 8;

    const int lrow = tid >> 3;
    const int lchk = (tid & 7) * 8;

    float acc[4][NFN][4] = {};
    const int niter = K / BK;

    auto load_stage = [&](int stage, int k0) {
        __half* Sa = sh + stage * STG_HALFS;
        __half* Sb = Sa + A_HALFS;
#pragma unroll
        for (int i = 0; i < BM / 32; i++) {
            int r = lrow + i * 32;
            cp_async16(&Sa[r * STRH + lchk], A + (size_t)(row0 + r) * K + k0 + lchk);
        }
#pragma unroll
        for (int i = 0; i < BN / 32; i++) {
            int r = lrow + i * 32;
            cp_async16(&Sb[r * STRH + lchk], B + (size_t)(col0 + r) * K + k0 + lchk);
        }
    };

    load_stage(0, 0);
    asm volatile("cp.async.commit_group;");
    if (niter > 1) load_stage(1, BK);
    asm volatile("cp.async.commit_group;");

    int s = 0;
    for (int it = 0; it < niter; it++) {
        asm volatile("cp.async.wait_group 1;");
        __syncthreads();                       // single barrier per iteration

        if (it + 2 < niter) load_stage((it + 2) % 3, (it + 2) * BK);
        asm volatile("cp.async.commit_group;");

        const uint32_t sA = sbase + (uint32_t)(s * STG_HALFS) * 2;
        const uint32_t sB = sA + A_HALFS * 2;
#pragma unroll
        for (int kk = 0; kk < BK / 16; kk++) {
            const int kb = kk * 16;
            uint32_t af[4][4], bf[NFN][2];
#pragma unroll
            for (int fm = 0; fm < 4; fm++)
                ldsm_x4(af[fm][0], af[fm][1], af[fm][2], af[fm][3],
                        sA + (uint32_t)((a_row + fm * 16) * STRH + kb + a_colh) * 2);
#pragma unroll
            for (int p = 0; p < NPAIR; p++)
                ldsm_x4(bf[2 * p][0], bf[2 * p][1], bf[2 * p + 1][0], bf[2 * p + 1][1],
                        sB + (uint32_t)((wn * WN + p * 16 + b_row) * STRH + kb + b_colh) * 2);
#pragma unroll
            for (int fm = 0; fm < 4; fm++)
#pragma unroll
                for (int fn = 0; fn < NFN; fn++)
                    mma_f16(acc[fm][fn], af[fm], bf[fn]);
        }
        s = (s + 1) % 3;
    }

#pragma unroll
    for (int fm = 0; fm < 4; fm++) {
        int r = row0 + wm * 64 + fm * 16 + gid;
#pragma unroll
        for (int fn = 0; fn < NFN; fn++) {
            int cbase = col0 + wn * WN + fn * 8 + t4 * 2;
            float2* p0 = (float2*)&C[(size_t)r * N + cbase];
            float2* p1 = (float2*)&C[(size_t)(r + 8) * N + cbase];
            *p0 = make_float2(acc[fm][fn][0], acc[fm][fn][1]);
            *p1 = make_float2(acc[fm][fn][2], acc[fm][fn][3]);
        }
    }
}

// ---------------------------------------------------------------------------
// fp32->fp16 conversion (split keeps xdbl_conv in profiled 4th launch slot)
// ---------------------------------------------------------------------------
#define N4_X  (TOKENS * DMODEL / 4)
#define N4_WI (2 * DINNER * DMODEL / 4)
#define N4_WO (DMODEL * DINNER / 4)

__global__ void cvt_xw_k(const float* __restrict__ x, const float* __restrict__ Wi) {
    int i = blockIdx.x * blockDim.x + threadIdx.x;
    const float* src; __half* dst; int off;
    if (i < N4_X)               { src = x;  dst = g_xh; off = i; }
    else if (i < N4_X + N4_WI)  { src = Wi; dst = g_wh; off = i - N4_X; }
    else return;
    float4 v = ((const float4*)src)[off];
    __half2 h0 = __float22half2_rn(make_float2(v.x, v.y));
    __half2 h1 = __float22half2_rn(make_float2(v.z, v.w));
    ((uint2*)dst)[off] = make_uint2(*(uint32_t*)&h0, *(uint32_t*)&h1);
}

__global__ void cvt_wo_k(const float* __restrict__ Wo) {
    int i = blockIdx.x * blockDim.x + threadIdx.x;
    if (i >= N4_WO) return;
    float4 v = ((const float4*)Wo)[i];
    __half2 h0 = __float22half2_rn(make_float2(v.x, v.y));
    __half2 h1 = __float22half2_rn(make_float2(v.z, v.w));
    ((uint2*)g_woh)[i] = make_uint2(*(uint32_t*)&h0, *(uint32_t*)&h1);
}

// ---------------------------------------------------------------------------
// Fused conv+SiLU + x_dbl partials, split-K 16.
// __launch_bounds__(264, 5) caps regs at 40 -> 5 CTAs/SM (occ 70%), fixing
// the measured warp-starvation (occ 48.4% ≈ issue 47.5%, L1 only 67.6%).
// ---------------------------------------------------------------------------
__global__ void __launch_bounds__(264, 5)
xdbl_conv_k(const float* __restrict__ Wx,
            const float* __restrict__ cw,
            const float* __restrict__ cb) {
    __shared__ float Sxz[67][36];
    __shared__ float Xs [64][33];
    __shared__ float Ws [33][33];
    __shared__ float Scw[32][5];
    const int tx = threadIdx.x, ty = threadIdx.y;   // (33,8)
    const int tid = ty * 33 + tx;
    const int tok0 = blockIdx.x * 64;
    const int kbase = blockIdx.y * 128;             // split-K 16
    const bool halo_ok = (tok0 & (SEQL - 1)) != 0;

    float acc[8] = {};

    for (int kc = 0; kc < 4; kc++) {
        const int k0 = kbase + kc * 32;
        for (int i = tid; i < 33 * 32; i += 264) {
            int e = i >> 5, kk = i & 31;
            Ws[e][kk] = Wx[(size_t)e * DINNER + k0 + kk];
        }
        if (tid < 32 * 5) {
            int kk = tid / 5, j = tid - kk * 5;
            Scw[kk][j] = (j < 4) ? cw[(k0 + kk) * 4 + j] : cb[k0 + kk];
        }
        for (int i = tid; i < 67 * 8; i += 264) {
            int row = i >> 3, c4 = (i & 7) * 4;
            float4 v = make_float4(0.f, 0.f, 0.f, 0.f);
            if (row >= 3 || halo_ok)
                v = *(const float4*)&g_xz[(size_t)(tok0 - 3 + row) * (2 * DINNER) + k0 + c4];
            *(float4*)&Sxz[row][c4] = v;
        }
        __syncthreads();

        for (int i = tid; i < 64 * 32; i += 264) {
            int tt = i >> 5, kk = i & 31;
            float a0 = Scw[kk][4];
            a0 = fmaf(Sxz[tt + 0][kk], Scw[kk][0], a0);
            a0 = fmaf(Sxz[tt + 1][kk], Scw[kk][1], a0);
            a0 = fmaf(Sxz[tt + 2][kk], Scw[kk][2], a0);
            a0 = fmaf(Sxz[tt + 3][kk], Scw[kk][3], a0);
            float xv = a0 / (1.f + __expf(-a0));
            Xs[tt][kk] = xv;
            g_xi[(size_t)(tok0 + tt) * DINNER + k0 + kk] = xv;
        }
        __syncthreads();

#pragma unroll
        for (int kk = 0; kk < 32; kk++) {
            float w = Ws[tx][kk];
#pragma unroll
            for (int i = 0; i < 8; i++)
                acc[i] = fmaf(Xs[ty * 8 + i][kk], w, acc[i]);
        }
        __syncthreads();
    }
#pragma unroll
    for (int i = 0; i < 8; i++)
        g_dbcp[blockIdx.y][(size_t)(tok0 + ty * 8 + i) * 33 + tx] = acc[i];
}

__global__ void xdbl_reduce_k() {
    int i = blockIdx.x * blockDim.x + threadIdx.x;
    if (i >= TOKENS * 33) return;
    float s = 0.f;
#pragma unroll
    for (int p = 0; p < 16; p++) s += g_dbcp[p][i];
    g_dbc[i] = s;
}

// ---------------------------------------------------------------------------
// Selective scan with cp.async double-buffered staging (unchanged from R13).
// ---------------------------------------------------------------------------
#define CH 32
#define CPB 8
#define PSTRIDE 17
#define NCHUNK (SEQL / CH)

__global__ void __launch_bounds__(128, 4)
scan_k(const float* __restrict__ A_log, const float* __restrict__ Dvec,
       const float* __restrict__ Wdt, const float* __restrict__ bdt) {
    __shared__ __align__(16) float  sDBC[2][CH * 33];
    __shared__ __align__(16) float  sXr [2][CH][8];
    __shared__ __align__(16) float  sZ  [2][CH][8];
    __shared__ __align__(16) float2 sDX [2][CH][8];   // (softplus(dt), xi)
    __shared__ float sP[CH][CPB * PSTRIDE];
    const int tid = threadIdx.x;              // 128
    const int dd = tid >> 4, n = tid & 15;
    const int q8 = tid & 7;
    const int b = blockIdx.y;
    const int d0 = blockIdx.x * CPB;

    const float a  = -__expf(A_log[(d0 + dd) * DSTATE + n]);
    const float wq = Wdt[d0 + q8];
    const float bq = bdt[d0 + q8];
    const float Dq = Dvec[d0 + q8];
    float h = 0.f;

    auto issue = [&](int c) {
        const int buf = c & 1;
        const int tok0 = b * SEQL + c * CH;
        const float* src = &g_dbc[(size_t)tok0 * 33];
#pragma unroll
        for (int j = 0; j < 3; j++) {
            int g = tid + j * 128;
            if (g < 264) cp_async16(&sDBC[buf][g * 4], src + g * 4);
        }
        if (tid < 64) {
            int token = tid >> 1, half = tid & 1;
            cp_async16(&sXr[buf][token][half * 4],
                       &g_xi[(size_t)(tok0 + token) * DINNER + d0 + half * 4]);
        } else {
            int t2 = tid - 64, token = t2 >> 1, half = t2 & 1;
            cp_async16(&sZ[buf][token][half * 4],
                       &g_xz[(size_t)(tok0 + token) * (2 * DINNER) + DINNER + d0 + half * 4]);
        }
        asm volatile("cp.async.commit_group;");
    };

    issue(0);
    for (int c = 0; c < NCHUNK; c++) {
        const int buf = c & 1;
        const int tok0 = b * SEQL + c * CH;
        asm volatile("cp.async.wait_group 0;");
        __syncthreads();

#pragma unroll
        for (int j = 0; j < 2; j++) {
            int tt = (tid + j * 128) >> 3;
            float u = sDBC[buf][tt * 33] * wq + bq;
            float sp = (u > 20.f) ? u : log1pf(__expf(u));
            sDX[buf][tt][q8] = make_float2(sp, sXr[buf][tt][q8]);
        }
        if (c + 1 < NCHUNK) issue(c + 1);
        __syncthreads();

        float dA[CH], bx[CH];
#pragma unroll
        for (int t = 0; t < CH; t++) {
            float2 dx = sDX[buf][t][dd];
            dA[t] = __expf(dx.x * a);
            bx[t] = (dx.x * sDBC[buf][t * 33 + 1 + n]) * dx.y;
        }
#pragma unroll
        for (int t = 0; t < CH; t++) {
            h = fmaf(dA[t], h, bx[t]);
            sP[t][dd * PSTRIDE + n] = h * sDBC[buf][t * 33 + 17 + n];
        }
        __syncthreads();

#pragma unroll
        for (int j = 0; j < 2; j++) {
            int i = tid + j * 128;
            int tt = i >> 3;
            float s = 0.f;
#pragma unroll
            for (int k = 0; k < 16; k++) s += sP[tt][q8 * PSTRIDE + k];
            float xv = sXr[buf][tt][q8], zv = sZ[buf][tt][q8];
            float yv = (s + Dq * xv) * (zv / (1.f + __expf(-zv)));
            g_yh[(size_t)(tok0 + tt) * DINNER + d0 + q8] = __float2half_rn(yv);
        }
    }
}

// ---------------------------------------------------------------------------
extern "C" void kernel_launch(void* const* d_in, const int* in_sizes, int n_in,
                              void* d_out, int out_size) {
    const float* x     = (const float*)d_in[0];
    const float* W_in  = (const float*)d_in[1];
    const float* convw = (const float*)d_in[2];
    const float* convb = (const float*)d_in[3];
    const float* W_x   = (const float*)d_in[4];
    const float* W_dt  = (const float*)d_in[5];
    const float* b_dt  = (const float*)d_in[6];
    const float* A_log = (const float*)d_in[7];
    const float* Dv    = (const float*)d_in[8];
    const float* W_out = (const float*)d_in[9];
    float* out = (float*)d_out;

    float *xz;
    __half *xh, *wh, *woh, *yh;
    cudaGetSymbolAddress((void**)&xz,  g_xz);
    cudaGetSymbolAddress((void**)&xh,  g_xh);
    cudaGetSymbolAddress((void**)&wh,  g_wh);
    cudaGetSymbolAddress((void**)&woh, g_woh);
    cudaGetSymbolAddress((void**)&yh,  g_yh);

    cudaFuncSetAttribute(h_gemm_nt, cudaFuncAttributeMaxDynamicSharedMemorySize, GEMM_SMEM);

    // 1-2) convert GEMM operands to fp16
    cvt_xw_k<<<(N4_X + N4_WI + 255) / 256, 256>>>(x, W_in);
    cvt_wo_k<<<(N4_WO + 255) / 256, 256>>>(W_out);

    // 3) xz = x @ W_in^T   [4096 x 4096], K=1024
    h_gemm_nt<<<dim3(4096 / BN, TOKENS / BM), 256, GEMM_SMEM>>>(xh, wh, xz, TOKENS, 4096, DMODEL);

    // 4) fused conv+silu + x_dbl partials (split-K 16)  [profiled slot]
    xdbl_conv_k<<<dim3(TOKENS / 64, 16), dim3(33, 8)>>>(W_x, convw, convb);

    // 5) deterministic split-K reduce
    xdbl_reduce_k<<<(TOKENS * 33 + 255) / 256, 256>>>();

    // 6) selective scan -> g_yh (half)
    scan_k<<<dim3(DINNER / CPB, 2), 128>>>(A_log, Dv, W_dt, b_dt);

    // 7) out = y @ W_out^T   [4096 x 1024], K=2048
    h_gemm_nt<<<dim3(DMODEL / BN, TOKENS / BM), 256, GEMM_SMEM>>>(yh, woh, out, TOKENS, DMODEL, DINNER);
}